// round 13
// baseline (speedup 1.0000x reference)
#include <cuda_runtime.h>
#include <cuda_bf16.h>
#include <math.h>
#include <stdint.h>

#define N_TOK 4096
#define CDIM 256
#define HEADS 16
#define DHEAD 64
#define HD 1024
#define NQ 64
#define NKEY 256
#define NTRUNK 64
#define PADL 96
#define KZ 4
#define NPERS 296   // persistent CTAs: 2 per SM x 148

extern __shared__ char dyn_smem[];

// ---------------- scratch (device globals) ----------------
__device__ float g_gate[N_TOK * HD];
__device__ float g_part[KZ * N_TOK * CDIM];

__device__ __align__(16) __nv_bfloat16 g_aq_hi[N_TOK * CDIM];
__device__ __align__(16) __nv_bfloat16 g_aq_lo[N_TOK * CDIM];
__device__ __align__(16) __nv_bfloat16 g_akv_hi[N_TOK * CDIM];
__device__ __align__(16) __nv_bfloat16 g_akv_lo[N_TOK * CDIM];
__device__ __align__(16) __nv_bfloat16 g_wt_hi[4 * HD * CDIM];   // [mat][n][k]
__device__ __align__(16) __nv_bfloat16 g_wt_lo[4 * HD * CDIM];
__device__ __align__(16) __nv_bfloat16 g_wot_hi[CDIM * HD];      // [n][k]
__device__ __align__(16) __nv_bfloat16 g_wot_lo[CDIM * HD];
__device__ __align__(16) __nv_bfloat16 g_og_hi[N_TOK * HD];
__device__ __align__(16) __nv_bfloat16 g_og_lo[N_TOK * HD];

// attention operands (bf16 hi/lo), q pre-scaled by 1/8
__device__ __align__(16) __nv_bfloat16 g_qh[HEADS * N_TOK * DHEAD];
__device__ __align__(16) __nv_bfloat16 g_ql[HEADS * N_TOK * DHEAD];
__device__ __align__(16) __nv_bfloat16 g_kh[HEADS * N_TOK * DHEAD];
__device__ __align__(16) __nv_bfloat16 g_kl[HEADS * N_TOK * DHEAD];
__device__ __align__(16) __nv_bfloat16 g_vth[HEADS * DHEAD * N_TOK]; // [h][d][n]
__device__ __align__(16) __nv_bfloat16 g_vtl[HEADS * DHEAD * N_TOK];

// ---------------- helpers ----------------
__device__ __forceinline__ uint32_t smem_u32(const void* p) {
    uint32_t a;
    asm("{ .reg .u64 t; cvta.to.shared.u64 t, %1; cvt.u32.u64 %0, t; }" : "=r"(a) : "l"(p));
    return a;
}

__device__ __forceinline__ void ldm_x4(uint32_t addr, uint32_t* r) {
    asm volatile("ldmatrix.sync.aligned.m8n8.x4.shared.b16 {%0,%1,%2,%3}, [%4];"
                 : "=r"(r[0]), "=r"(r[1]), "=r"(r[2]), "=r"(r[3]) : "r"(addr));
}

__device__ __forceinline__ void mma16816(float* c, const uint32_t* a, uint32_t b0, uint32_t b1) {
    asm volatile(
        "mma.sync.aligned.m16n8k16.row.col.f32.bf16.bf16.f32 "
        "{%0,%1,%2,%3}, {%4,%5,%6,%7}, {%8,%9}, {%0,%1,%2,%3};"
        : "+f"(c[0]), "+f"(c[1]), "+f"(c[2]), "+f"(c[3])
        : "r"(a[0]), "r"(a[1]), "r"(a[2]), "r"(a[3]), "r"(b0), "r"(b1));
}

__device__ __forceinline__ uint32_t pack_bf16x2(float x0, float x1) {
    __nv_bfloat162 p;
    p.x = __float2bfloat16(x0);
    p.y = __float2bfloat16(x1);
    return *(uint32_t*)&p;
}

__device__ __forceinline__ void split2(float x0, float x1,
                                       __nv_bfloat162* hi, __nv_bfloat162* lo) {
    __nv_bfloat16 b0 = __float2bfloat16(x0), b1 = __float2bfloat16(x1);
    hi->x = b0; hi->y = b1;
    lo->x = __float2bfloat16(x0 - __bfloat162float(b0));
    lo->y = __float2bfloat16(x1 - __bfloat162float(b1));
}

__device__ __forceinline__ void cp16(uint32_t d, const void* s) {
    asm volatile("cp.async.cg.shared.global [%0], [%1], 16;" :: "r"(d), "l"(s));
}

// GEMM smem: BK=32, pitch 40 halfwords; 4 regions of 10240 B; 2 stages.
#define SPITCH 40
#define RGN (128 * SPITCH)
#define AHOFF 0
#define ALOFF 10240
#define BHOFF 20480
#define BLOFF 30720
#define STG_BYTES 40960
#define SMEM_GEMM (2 * STG_BYTES)

__device__ __forceinline__ void mma_chunk(
    const __nv_bfloat16* sbuf, int wm, int wn, int lrow, int lcolh, float acc[4][4][4])
{
    #pragma unroll
    for (int ks = 0; ks < 2; ks++) {
        uint32_t ah[4][4], al[4][4];
        #pragma unroll
        for (int mt = 0; mt < 4; mt++) {
            int ro = (wm * 64 + mt * 16 + lrow) * SPITCH + ks * 16 + lcolh;
            ldm_x4(smem_u32(&sbuf[ro]), ah[mt]);
            ldm_x4(smem_u32(&sbuf[RGN + ro]), al[mt]);
        }
        #pragma unroll
        for (int bt = 0; bt < 2; bt++) {
            uint32_t bh[4], bl[4];
            int ro = (wn * 32 + bt * 16 + lrow) * SPITCH + ks * 16 + lcolh;
            ldm_x4(smem_u32(&sbuf[2 * RGN + ro]), bh);
            ldm_x4(smem_u32(&sbuf[3 * RGN + ro]), bl);
            #pragma unroll
            for (int mt = 0; mt < 4; mt++) {
                mma16816(acc[mt][bt * 2],     ah[mt], bh[0], bh[2]);
                mma16816(acc[mt][bt * 2],     al[mt], bh[0], bh[2]);
                mma16816(acc[mt][bt * 2],     ah[mt], bl[0], bl[2]);
                mma16816(acc[mt][bt * 2 + 1], ah[mt], bh[1], bh[3]);
                mma16816(acc[mt][bt * 2 + 1], al[mt], bh[1], bh[3]);
                mma16816(acc[mt][bt * 2 + 1], ah[mt], bl[1], bl[3]);
            }
        }
    }
}

// cp.async 2-stage pipelined GEMM mainloop (all operands bf16, K-major)
__device__ __forceinline__ void gemm_pipe(
    const __nv_bfloat16* __restrict__ Ah, const __nv_bfloat16* __restrict__ Al,
    const __nv_bfloat16* __restrict__ Bh, const __nv_bfloat16* __restrict__ Bl,
    int K, int kstart, int nk, float acc[4][4][4])
{
    const int tid = threadIdx.x, lane = tid & 31, warp = tid >> 5;
    const int wm = warp >> 2, wn = warp & 3;
    const int lrow = lane & 15, lcolh = (lane >> 4) * 8;
    const uint32_t sbase = smem_u32(dyn_smem);

    const int r0 = tid >> 2, g0 = (tid & 3) * 8;
    const int r1 = (tid + 256) >> 2, g1 = ((tid + 256) & 3) * 8;
    const uint32_t ds0 = (uint32_t)(r0 * SPITCH + g0) * 2;
    const uint32_t ds1 = (uint32_t)(r1 * SPITCH + g1) * 2;

    {
        int kb = kstart;
        size_t o0 = (size_t)r0 * K + kb + g0;
        size_t o1 = (size_t)r1 * K + kb + g1;
        uint32_t b = sbase;
        cp16(b + AHOFF + ds0, Ah + o0); cp16(b + AHOFF + ds1, Ah + o1);
        cp16(b + ALOFF + ds0, Al + o0); cp16(b + ALOFF + ds1, Al + o1);
        cp16(b + BHOFF + ds0, Bh + o0); cp16(b + BHOFF + ds1, Bh + o1);
        cp16(b + BLOFF + ds0, Bl + o0); cp16(b + BLOFF + ds1, Bl + o1);
        asm volatile("cp.async.commit_group;");
    }

    for (int i = 0; i < nk; i++) {
        if (i + 1 < nk) {
            int kb = kstart + (i + 1) * 32;
            size_t o0 = (size_t)r0 * K + kb + g0;
            size_t o1 = (size_t)r1 * K + kb + g1;
            uint32_t b = sbase + ((i + 1) & 1) * STG_BYTES;
            cp16(b + AHOFF + ds0, Ah + o0); cp16(b + AHOFF + ds1, Ah + o1);
            cp16(b + ALOFF + ds0, Al + o0); cp16(b + ALOFF + ds1, Al + o1);
            cp16(b + BHOFF + ds0, Bh + o0); cp16(b + BHOFF + ds1, Bh + o1);
            cp16(b + BLOFF + ds0, Bl + o0); cp16(b + BLOFF + ds1, Bl + o1);
            asm volatile("cp.async.commit_group;");
            asm volatile("cp.async.wait_group 1;");
        } else {
            asm volatile("cp.async.wait_group 0;");
        }
        __syncthreads();
        mma_chunk((const __nv_bfloat16*)(dyn_smem + (i & 1) * STG_BYTES),
                  wm, wn, lrow, lcolh, acc);
        __syncthreads();
    }
}

// ---------------------------------------------------------------------------
// merged conversions: z 0-1 = activations, z 2-6 = weights
// ---------------------------------------------------------------------------
__global__ __launch_bounds__(256) void conv_all(
    const float* __restrict__ qx, const float* __restrict__ kvx,
    const float* __restrict__ Wq, const float* __restrict__ Wk,
    const float* __restrict__ Wv, const float* __restrict__ Wg,
    const float* __restrict__ Wo)
{
    int z = blockIdx.z;
    if (z < 2) {
        const float* src = z ? kvx : qx;
        __nv_bfloat16* hi = z ? g_akv_hi : g_aq_hi;
        __nv_bfloat16* lo = z ? g_akv_lo : g_aq_lo;
        int base = (blockIdx.y * 32 + blockIdx.x) * 256 + threadIdx.x;
        #pragma unroll
        for (int i = 0; i < 4; i++) {
            int idx = base + i * (1024 * 256);
            float x = src[idx];
            __nv_bfloat16 h = __float2bfloat16(x);
            hi[idx] = h;
            lo[idx] = __float2bfloat16(x - __bfloat162float(h));
        }
        return;
    }
    int w = z - 2;
    const float* in; int R, C; __nv_bfloat16 *oh, *ol;
    if (w < 4) {
        in = (w == 0) ? Wq : (w == 1) ? Wk : (w == 2) ? Wv : Wg;
        R = CDIM; C = HD; oh = g_wt_hi + (size_t)w * HD * CDIM; ol = g_wt_lo + (size_t)w * HD * CDIM;
    } else {
        in = Wo; R = HD; C = CDIM; oh = g_wot_hi; ol = g_wot_lo;
    }
    int c0 = blockIdx.x * 32, r0 = blockIdx.y * 32;
    if (c0 >= C || r0 >= R) return;
    __shared__ float t[32][33];
    int tx = threadIdx.x & 31, ty = threadIdx.x >> 5;
    for (int i = ty; i < 32; i += 8) t[i][tx] = in[(size_t)(r0 + i) * C + c0 + tx];
    __syncthreads();
    for (int i = ty; i < 32; i += 8) {
        float x = t[tx][i];
        __nv_bfloat16 h = __float2bfloat16(x);
        size_t o = (size_t)(c0 + i) * R + r0 + tx;
        oh[o] = h;
        ol[o] = __float2bfloat16(x - __bfloat162float(h));
    }
}

// ---------------------------------------------------------------------------
// projection GEMMs: persistent CTAs over 1024 tiles (8 nx, 32 my, 4 mats)
// ---------------------------------------------------------------------------
#define TPT 136

__global__ __launch_bounds__(256, 2) void mm_proj_tc()
{
    const int tid = threadIdx.x, lane = tid & 31, warp = tid >> 5;
    const int wm = warp >> 2, wn = warp & 3;
    const int l4 = lane >> 2, lq = lane & 3;

    for (int tile = blockIdx.x; tile < 1024; tile += NPERS) {
        __syncthreads();   // protect smem reuse across tiles
        const int mat = tile >> 8;
        const int rem = tile & 255;
        const int m0 = (rem >> 3) * 128, n0 = (rem & 7) * 128;
        const __nv_bfloat16* Ah = ((mat == 1 || mat == 2) ? g_akv_hi : g_aq_hi) + (size_t)m0 * CDIM;
        const __nv_bfloat16* Al = ((mat == 1 || mat == 2) ? g_akv_lo : g_aq_lo) + (size_t)m0 * CDIM;
        const __nv_bfloat16* Bh = g_wt_hi + (size_t)mat * HD * CDIM + (size_t)n0 * CDIM;
        const __nv_bfloat16* Bl = g_wt_lo + (size_t)mat * HD * CDIM + (size_t)n0 * CDIM;

        float acc[4][4][4] = {};
        gemm_pipe(Ah, Al, Bh, Bl, CDIM, 0, CDIM / 32, acc);

        if (mat == 2) {
            __nv_bfloat16* sT = (__nv_bfloat16*)dyn_smem;
            #pragma unroll
            for (int pass = 0; pass < 2; pass++) {
                #pragma unroll
                for (int mt = 0; mt < 4; mt++) {
                    #pragma unroll
                    for (int nt = 0; nt < 4; nt++) {
                        #pragma unroll
                        for (int rr = 0; rr < 2; rr++) {
                            int ml = wm * 64 + mt * 16 + l4 + rr * 8;
                            int cl = wn * 32 + nt * 8 + lq * 2;
                            float v0 = acc[mt][nt][rr * 2], v1 = acc[mt][nt][rr * 2 + 1];
                            __nv_bfloat16 b0 = __float2bfloat16(v0), b1 = __float2bfloat16(v1);
                            if (pass == 0) {
                                sT[cl * TPT + ml] = b0;
                                sT[(cl + 1) * TPT + ml] = b1;
                            } else {
                                sT[cl * TPT + ml] = __float2bfloat16(v0 - __bfloat162float(b0));
                                sT[(cl + 1) * TPT + ml] = __float2bfloat16(v1 - __bfloat162float(b1));
                            }
                        }
                    }
                }
                __syncthreads();
                {
                    int cl = tid >> 1, half = tid & 1;
                    int hh = (n0 + cl) >> 6, d = (n0 + cl) & 63;
                    __nv_bfloat16* dst = (pass == 0 ? g_vth : g_vtl)
                                       + ((size_t)hh * DHEAD + d) * N_TOK + m0 + half * 64;
                    const __nv_bfloat16* srcr = &sT[cl * TPT + half * 64];
                    #pragma unroll
                    for (int j = 0; j < 8; j++)
                        *(uint4*)&dst[j * 8] = *(const uint4*)&srcr[j * 8];
                }
                __syncthreads();
            }
        } else {
            #pragma unroll
            for (int mt = 0; mt < 4; mt++) {
                #pragma unroll
                for (int nt = 0; nt < 4; nt++) {
                    #pragma unroll
                    for (int rr = 0; rr < 2; rr++) {
                        int m = m0 + wm * 64 + mt * 16 + l4 + rr * 8;
                        int c = n0 + wn * 32 + nt * 8 + lq * 2;
                        float v0 = acc[mt][nt][rr * 2], v1 = acc[mt][nt][rr * 2 + 1];
                        int hh = c >> 6, d = c & 63;
                        if (mat == 0) {
                            __nv_bfloat162 ph, pl;
                            split2(v0 * 0.125f, v1 * 0.125f, &ph, &pl);
                            size_t o = ((size_t)hh * N_TOK + m) * DHEAD + d;
                            *(__nv_bfloat162*)&g_qh[o] = ph;
                            *(__nv_bfloat162*)&g_ql[o] = pl;
                        } else if (mat == 1) {
                            __nv_bfloat162 ph, pl;
                            split2(v0, v1, &ph, &pl);
                            size_t o = ((size_t)hh * N_TOK + m) * DHEAD + d;
                            *(__nv_bfloat162*)&g_kh[o] = ph;
                            *(__nv_bfloat162*)&g_kl[o] = pl;
                        } else {
                            float2 v = make_float2(1.f / (1.f + expf(-v0)), 1.f / (1.f + expf(-v1)));
                            *(float2*)&g_gate[(size_t)m * HD + c] = v;
                        }
                    }
                }
            }
        }
    }
}

// ---------------------------------------------------------------------------
// output GEMM, split-K pipelined: grid (2, 32, KZ) — single wave
// ---------------------------------------------------------------------------
__global__ __launch_bounds__(256, 2) void mm_out_tc()
{
    const int m0 = blockIdx.y * 128, n0 = blockIdx.x * 128;
    const int kz = blockIdx.z;

    float acc[4][4][4] = {};
    gemm_pipe(g_og_hi + (size_t)m0 * HD, g_og_lo + (size_t)m0 * HD,
              g_wot_hi + (size_t)n0 * HD, g_wot_lo + (size_t)n0 * HD,
              HD, kz * (HD / KZ), (HD / KZ) / 32, acc);

    float* part = g_part + (size_t)kz * N_TOK * CDIM;
    const int lane = threadIdx.x & 31, warp = threadIdx.x >> 5;
    const int wm = warp >> 2, wn = warp & 3;
    const int l4 = lane >> 2, lq = lane & 3;
    #pragma unroll
    for (int mt = 0; mt < 4; mt++) {
        #pragma unroll
        for (int nt = 0; nt < 4; nt++) {
            #pragma unroll
            for (int rr = 0; rr < 2; rr++) {
                int m = m0 + wm * 64 + mt * 16 + l4 + rr * 8;
                int c = n0 + wn * 32 + nt * 8 + lq * 2;
                *(float2*)&part[(size_t)m * CDIM + c] =
                    make_float2(acc[mt][nt][rr * 2], acc[mt][nt][rr * 2 + 1]);
            }
        }
    }
}

__global__ __launch_bounds__(256) void reduce_out(float* __restrict__ out)
{
    int idx = (blockIdx.x * 256 + threadIdx.x) * 4;
    float4 a = *(const float4*)&g_part[idx];
    float4 b = *(const float4*)&g_part[N_TOK * CDIM + idx];
    float4 c = *(const float4*)&g_part[2 * N_TOK * CDIM + idx];
    float4 d = *(const float4*)&g_part[3 * N_TOK * CDIM + idx];
    float4 r = make_float4(a.x + b.x + c.x + d.x, a.y + b.y + c.y + d.y,
                           a.z + b.z + c.z + d.z, a.w + b.w + c.w + d.w);
    *(float4*)&out[idx] = r;
}

// ---------------------------------------------------------------------------
// tensor-core local attention — persistent over 1024 (h,t) pairs
// ---------------------------------------------------------------------------
#define QP 72
#define VP 264

__global__ __launch_bounds__(256) void attn_tc(const float* __restrict__ bias)
{
    __nv_bfloat16* Sb = (__nv_bfloat16*)dyn_smem;
    __nv_bfloat16* sQh = Sb;
    __nv_bfloat16* sQl = Sb + 4608;
    __nv_bfloat16* sKh = Sb + 9216;
    __nv_bfloat16* sKl = Sb + 27648;
    __nv_bfloat16* sVh = Sb + 9216;
    __nv_bfloat16* sVl = Sb + 26112;
    float* sO = (float*)dyn_smem;
    float* pm = (float*)(dyn_smem + 92160);
    float* ps = (float*)(dyn_smem + 92672);

    const int tid = threadIdx.x, lane = tid & 31, warp = tid >> 5;
    const int wm = warp & 3, ch = warp >> 2;
    const int lrow = lane & 15, lcolh = (lane >> 4) * 8;
    const int l4 = lane >> 2, lq = lane & 3;
    const int rloc = wm * 16 + l4;

    for (int job = blockIdx.x; job < HEADS * NTRUNK; job += NPERS) {
        __syncthreads();   // protect smem overlays across jobs
        const int h = job & (HEADS - 1), t = job >> 4;
        const int kbase = t * NQ - PADL;

        {
            const __nv_bfloat16* qh = g_qh + ((size_t)h * N_TOK + t * NQ) * DHEAD;
            const __nv_bfloat16* ql = g_ql + ((size_t)h * N_TOK + t * NQ) * DHEAD;
            #pragma unroll
            for (int i = 0; i < 2; i++) {
                int idx = tid + i * 256;
                int r = idx >> 3, g = idx & 7;
                *(uint4*)&sQh[r * QP + g * 8] = *(const uint4*)&qh[idx * 8];
                *(uint4*)&sQl[r * QP + g * 8] = *(const uint4*)&ql[idx * 8];
            }
            #pragma unroll
            for (int i = 0; i < 8; i++) {
                int idx = tid + i * 256;
                int r = idx >> 3, g = idx & 7;
                int gk = kbase + r;
                uint4 vh = {0, 0, 0, 0}, vl = {0, 0, 0, 0};
                if (gk >= 0 && gk < N_TOK) {
                    size_t src = ((size_t)h * N_TOK + gk) * DHEAD + g * 8;
                    vh = *(const uint4*)&g_kh[src];
                    vl = *(const uint4*)&g_kl[src];
                }
                *(uint4*)&sKh[r * QP + g * 8] = vh;
                *(uint4*)&sKl[r * QP + g * 8] = vl;
            }
        }

        float acc[16][4];
        {
            const int r0 = t * NQ + wm * 16 + l4;
            const int c0 = kbase + ch * 128 + lq * 2;
            #pragma unroll
            for (int nt = 0; nt < 16; nt++) {
                int gc = c0 + nt * 8;
                if (gc >= 0 && gc < N_TOK) {
                    float2 b0 = *(const float2*)&bias[(size_t)r0 * N_TOK + gc];
                    float2 b1 = *(const float2*)&bias[(size_t)(r0 + 8) * N_TOK + gc];
                    acc[nt][0] = b0.x; acc[nt][1] = b0.y;
                    acc[nt][2] = b1.x; acc[nt][3] = b1.y;
                } else {
                    acc[nt][0] = 0.f; acc[nt][1] = 0.f; acc[nt][2] = 0.f; acc[nt][3] = 0.f;
                }
            }
        }
        __syncthreads();

        uint32_t ah[4][4], al[4][4];
        #pragma unroll
        for (int kc = 0; kc < 4; kc++) {
            int ro = (wm * 16 + lrow) * QP + kc * 16 + lcolh;
            ldm_x4(smem_u32(&sQh[ro]), ah[kc]);
            ldm_x4(smem_u32(&sQl[ro]), al[kc]);
        }
        #pragma unroll
        for (int nt = 0; nt < 8; nt++) {
            #pragma unroll
            for (int kc = 0; kc < 4; kc++) {
                uint32_t bh[4], bl[4];
                int ro = (ch * 128 + nt * 16 + lrow) * QP + kc * 16 + lcolh;
                ldm_x4(smem_u32(&sKh[ro]), bh);
                ldm_x4(smem_u32(&sKl[ro]), bl);
                mma16816(acc[2 * nt],     ah[kc], bh[0], bh[2]);
                mma16816(acc[2 * nt],     al[kc], bh[0], bh[2]);
                mma16816(acc[2 * nt],     ah[kc], bl[0], bl[2]);
                mma16816(acc[2 * nt + 1], ah[kc], bh[1], bh[3]);
                mma16816(acc[2 * nt + 1], al[kc], bh[1], bh[3]);
                mma16816(acc[2 * nt + 1], ah[kc], bl[1], bl[3]);
            }
        }

        float mx0 = -1e30f, mx1 = -1e30f;
        #pragma unroll
        for (int nt = 0; nt < 16; nt++) {
            mx0 = fmaxf(mx0, fmaxf(acc[nt][0], acc[nt][1]));
            mx1 = fmaxf(mx1, fmaxf(acc[nt][2], acc[nt][3]));
        }
        mx0 = fmaxf(mx0, __shfl_xor_sync(0xffffffffu, mx0, 1));
        mx0 = fmaxf(mx0, __shfl_xor_sync(0xffffffffu, mx0, 2));
        mx1 = fmaxf(mx1, __shfl_xor_sync(0xffffffffu, mx1, 1));
        mx1 = fmaxf(mx1, __shfl_xor_sync(0xffffffffu, mx1, 2));
        if (lq == 0) { pm[ch * 64 + rloc] = mx0; pm[ch * 64 + rloc + 8] = mx1; }
        __syncthreads();   // all sK reads retired; pm visible

        // V load overlaps the exp/sum math below
        #pragma unroll
        for (int i = 0; i < 8; i++) {
            int idx = tid + i * 256;
            int d = idx >> 5, g = idx & 31;
            int gk0 = kbase + g * 8;
            uint4 vh = {0, 0, 0, 0}, vl = {0, 0, 0, 0};
            if (gk0 >= 0 && gk0 < N_TOK) {
                size_t src = ((size_t)h * DHEAD + d) * N_TOK + gk0;
                vh = *(const uint4*)&g_vth[src];
                vl = *(const uint4*)&g_vtl[src];
            }
            *(uint4*)&sVh[d * VP + g * 8] = vh;
            *(uint4*)&sVl[d * VP + g * 8] = vl;
        }

        float M0 = fmaxf(pm[rloc], pm[64 + rloc]);
        float M1 = fmaxf(pm[rloc + 8], pm[64 + rloc + 8]);
        float s0 = 0.f, s1 = 0.f;
        #pragma unroll
        for (int nt = 0; nt < 16; nt++) {
            acc[nt][0] = __expf(acc[nt][0] - M0); s0 += acc[nt][0];
            acc[nt][1] = __expf(acc[nt][1] - M0); s0 += acc[nt][1];
            acc[nt][2] = __expf(acc[nt][2] - M1); s1 += acc[nt][2];
            acc[nt][3] = __expf(acc[nt][3] - M1); s1 += acc[nt][3];
        }
        s0 += __shfl_xor_sync(0xffffffffu, s0, 1);
        s0 += __shfl_xor_sync(0xffffffffu, s0, 2);
        s1 += __shfl_xor_sync(0xffffffffu, s1, 1);
        s1 += __shfl_xor_sync(0xffffffffu, s1, 2);
        if (lq == 0) { ps[ch * 64 + rloc] = s0; ps[ch * 64 + rloc + 8] = s1; }
        __syncthreads();   // ps visible + V resident

        float inv0 = 1.f / (ps[rloc] + ps[64 + rloc]);
        float inv1 = 1.f / (ps[rloc + 8] + ps[64 + rloc + 8]);
        #pragma unroll
        for (int nt = 0; nt < 16; nt++) {
            acc[nt][0] *= inv0; acc[nt][1] *= inv0;
            acc[nt][2] *= inv1; acc[nt][3] *= inv1;
        }

        float oacc[8][4];
        #pragma unroll
        for (int i = 0; i < 8; i++) { oacc[i][0] = 0.f; oacc[i][1] = 0.f; oacc[i][2] = 0.f; oacc[i][3] = 0.f; }
        #pragma unroll
        for (int kc = 0; kc < 8; kc++) {
            uint32_t awh[4], awl[4];
            #pragma unroll
            for (int f = 0; f < 4; f++) {
                int nt = 2 * kc + (f >> 1);
                int j = (f & 1) * 2;
                float x0 = acc[nt][j], x1 = acc[nt][j + 1];
                __nv_bfloat16 b0 = __float2bfloat16(x0), b1 = __float2bfloat16(x1);
                __nv_bfloat162 ph; ph.x = b0; ph.y = b1;
                awh[f] = *(uint32_t*)&ph;
                awl[f] = pack_bf16x2(x0 - __bfloat162float(b0), x1 - __bfloat162float(b1));
            }
            #pragma unroll
            for (int dg = 0; dg < 4; dg++) {
                uint32_t bh[4], bl[4];
                int ro = (dg * 16 + lrow) * VP + ch * 128 + kc * 16 + lcolh;
                ldm_x4(smem_u32(&sVh[ro]), bh);
                ldm_x4(smem_u32(&sVl[ro]), bl);
                mma16816(oacc[2 * dg],     awh, bh[0], bh[2]);
                mma16816(oacc[2 * dg],     awl, bh[0], bh[2]);
                mma16816(oacc[2 * dg],     awh, bl[0], bl[2]);
                mma16816(oacc[2 * dg + 1], awh, bh[1], bh[3]);
                mma16816(oacc[2 * dg + 1], awl, bh[1], bh[3]);
                mma16816(oacc[2 * dg + 1], awh, bl[1], bl[3]);
            }
        }

        __syncthreads();
        if (ch == 1) {
            #pragma unroll
            for (int nt = 0; nt < 8; nt++) {
                int c = nt * 8 + lq * 2;
                sO[(wm * 16 + l4) * 66 + c] = oacc[nt][0];
                sO[(wm * 16 + l4) * 66 + c + 1] = oacc[nt][1];
                sO[(wm * 16 + l4 + 8) * 66 + c] = oacc[nt][2];
                sO[(wm * 16 + l4 + 8) * 66 + c + 1] = oacc[nt][3];
            }
        }
        __syncthreads();
        if (ch == 0) {
            #pragma unroll
            for (int nt = 0; nt < 8; nt++) {
                int r = wm * 16 + l4, c = nt * 8 + lq * 2;
                #pragma unroll
                for (int half = 0; half < 2; half++) {
                    int rr = r + half * 8;
                    float v0 = oacc[nt][half * 2]     + sO[rr * 66 + c];
                    float v1 = oacc[nt][half * 2 + 1] + sO[rr * 66 + c + 1];
                    size_t gi = (size_t)(t * NQ + rr) * HD + h * DHEAD + c;
                    float2 gt = *(const float2*)&g_gate[gi];
                    __nv_bfloat162 ph, pl;
                    split2(v0 * gt.x, v1 * gt.y, &ph, &pl);
                    *(__nv_bfloat162*)&g_og_hi[gi] = ph;
                    *(__nv_bfloat162*)&g_og_lo[gi] = pl;
                }
            }
        }
    }
}

// ---------------------------------------------------------------------------
extern "C" void kernel_launch(void* const* d_in, const int* in_sizes, int n_in,
                              void* d_out, int out_size)
{
    const float* qx   = (const float*)d_in[0];
    const float* kvx  = (const float*)d_in[1];
    const float* bias = (const float*)d_in[2];
    const float* Wq   = (const float*)d_in[3];
    const float* Wk   = (const float*)d_in[4];
    const float* Wv   = (const float*)d_in[5];
    const float* Wg   = (const float*)d_in[6];
    const float* Wo   = (const float*)d_in[7];
    float* out = (float*)d_out;

    static int configured = 0;
    if (!configured) {
        cudaFuncSetAttribute(attn_tc, cudaFuncAttributeMaxDynamicSharedMemorySize, 93184);
        cudaFuncSetAttribute(mm_proj_tc, cudaFuncAttributeMaxDynamicSharedMemorySize, SMEM_GEMM);
        cudaFuncSetAttribute(mm_out_tc, cudaFuncAttributeMaxDynamicSharedMemorySize, SMEM_GEMM);
        configured = 1;
    }

    conv_all<<<dim3(32, 32, 7), 256>>>(qx, kvx, Wq, Wk, Wv, Wg, Wo);

    mm_proj_tc<<<NPERS, 256, SMEM_GEMM>>>();

    attn_tc<<<NPERS, 256, 93184>>>(bias);

    mm_out_tc<<<dim3(CDIM / 128, N_TOK / 128, KZ), 256, SMEM_GEMM>>>();
    reduce_out<<<N_TOK * CDIM / 1024, 256>>>(out);
}

// round 14
// speedup vs baseline: 1.1544x; 1.1544x over previous
#include <cuda_runtime.h>
#include <cuda_bf16.h>
#include <math.h>
#include <stdint.h>

#define N_TOK 4096
#define CDIM 256
#define HEADS 16
#define DHEAD 64
#define HD 1024
#define NQ 64
#define NKEY 256
#define NTRUNK 64
#define PADL 96
#define KZ 4

extern __shared__ char dyn_smem[];

// ---------------- scratch (device globals) ----------------
__device__ float g_gate[N_TOK * HD];
__device__ float g_part[KZ * N_TOK * CDIM];

__device__ __align__(16) __nv_bfloat16 g_aq_hi[N_TOK * CDIM];
__device__ __align__(16) __nv_bfloat16 g_aq_lo[N_TOK * CDIM];
__device__ __align__(16) __nv_bfloat16 g_akv_hi[N_TOK * CDIM];
__device__ __align__(16) __nv_bfloat16 g_akv_lo[N_TOK * CDIM];
__device__ __align__(16) __nv_bfloat16 g_wt_hi[4 * HD * CDIM];   // [mat][n][k]
__device__ __align__(16) __nv_bfloat16 g_wt_lo[4 * HD * CDIM];
__device__ __align__(16) __nv_bfloat16 g_wot_hi[CDIM * HD];      // [n][k]
__device__ __align__(16) __nv_bfloat16 g_wot_lo[CDIM * HD];
__device__ __align__(16) __nv_bfloat16 g_og_hi[N_TOK * HD];
__device__ __align__(16) __nv_bfloat16 g_og_lo[N_TOK * HD];

// attention operands (bf16 hi/lo), q pre-scaled by 1/8
__device__ __align__(16) __nv_bfloat16 g_qh[HEADS * N_TOK * DHEAD];
__device__ __align__(16) __nv_bfloat16 g_ql[HEADS * N_TOK * DHEAD];
__device__ __align__(16) __nv_bfloat16 g_kh[HEADS * N_TOK * DHEAD];
__device__ __align__(16) __nv_bfloat16 g_kl[HEADS * N_TOK * DHEAD];
__device__ __align__(16) __nv_bfloat16 g_vth[HEADS * DHEAD * N_TOK]; // [h][d][n]
__device__ __align__(16) __nv_bfloat16 g_vtl[HEADS * DHEAD * N_TOK];

// ---------------- helpers ----------------
__device__ __forceinline__ uint32_t smem_u32(const void* p) {
    uint32_t a;
    asm("{ .reg .u64 t; cvta.to.shared.u64 t, %1; cvt.u32.u64 %0, t; }" : "=r"(a) : "l"(p));
    return a;
}

__device__ __forceinline__ void ldm_x4(uint32_t addr, uint32_t* r) {
    asm volatile("ldmatrix.sync.aligned.m8n8.x4.shared.b16 {%0,%1,%2,%3}, [%4];"
                 : "=r"(r[0]), "=r"(r[1]), "=r"(r[2]), "=r"(r[3]) : "r"(addr));
}

__device__ __forceinline__ void mma16816(float* c, const uint32_t* a, uint32_t b0, uint32_t b1) {
    asm volatile(
        "mma.sync.aligned.m16n8k16.row.col.f32.bf16.bf16.f32 "
        "{%0,%1,%2,%3}, {%4,%5,%6,%7}, {%8,%9}, {%0,%1,%2,%3};"
        : "+f"(c[0]), "+f"(c[1]), "+f"(c[2]), "+f"(c[3])
        : "r"(a[0]), "r"(a[1]), "r"(a[2]), "r"(a[3]), "r"(b0), "r"(b1));
}

__device__ __forceinline__ uint32_t pack_bf16x2(float x0, float x1) {
    __nv_bfloat162 p;
    p.x = __float2bfloat16(x0);
    p.y = __float2bfloat16(x1);
    return *(uint32_t*)&p;
}

__device__ __forceinline__ void split2(float x0, float x1,
                                       __nv_bfloat162* hi, __nv_bfloat162* lo) {
    __nv_bfloat16 b0 = __float2bfloat16(x0), b1 = __float2bfloat16(x1);
    hi->x = b0; hi->y = b1;
    lo->x = __float2bfloat16(x0 - __bfloat162float(b0));
    lo->y = __float2bfloat16(x1 - __bfloat162float(b1));
}

__device__ __forceinline__ void cp16(uint32_t d, const void* s) {
    asm volatile("cp.async.cg.shared.global [%0], [%1], 16;" :: "r"(d), "l"(s));
}

// GEMM smem: BK=32, pitch 40 halfwords; 4 regions of 10240 B; 2 stages.
#define SPITCH 40
#define RGN (128 * SPITCH)
#define AHOFF 0
#define ALOFF 10240
#define BHOFF 20480
#define BLOFF 30720
#define STG_BYTES 40960
#define SMEM_GEMM (2 * STG_BYTES)

__device__ __forceinline__ void mma_chunk(
    const __nv_bfloat16* sbuf, int wm, int wn, int lrow, int lcolh, float acc[4][4][4])
{
    #pragma unroll
    for (int ks = 0; ks < 2; ks++) {
        uint32_t ah[4][4], al[4][4];
        #pragma unroll
        for (int mt = 0; mt < 4; mt++) {
            int ro = (wm * 64 + mt * 16 + lrow) * SPITCH + ks * 16 + lcolh;
            ldm_x4(smem_u32(&sbuf[ro]), ah[mt]);
            ldm_x4(smem_u32(&sbuf[RGN + ro]), al[mt]);
        }
        #pragma unroll
        for (int bt = 0; bt < 2; bt++) {
            uint32_t bh[4], bl[4];
            int ro = (wn * 32 + bt * 16 + lrow) * SPITCH + ks * 16 + lcolh;
            ldm_x4(smem_u32(&sbuf[2 * RGN + ro]), bh);
            ldm_x4(smem_u32(&sbuf[3 * RGN + ro]), bl);
            #pragma unroll
            for (int mt = 0; mt < 4; mt++) {
                mma16816(acc[mt][bt * 2],     ah[mt], bh[0], bh[2]);
                mma16816(acc[mt][bt * 2],     al[mt], bh[0], bh[2]);
                mma16816(acc[mt][bt * 2],     ah[mt], bl[0], bl[2]);
                mma16816(acc[mt][bt * 2 + 1], ah[mt], bh[1], bh[3]);
                mma16816(acc[mt][bt * 2 + 1], al[mt], bh[1], bh[3]);
                mma16816(acc[mt][bt * 2 + 1], ah[mt], bl[1], bl[3]);
            }
        }
    }
}

// cp.async 2-stage pipelined GEMM mainloop (all operands bf16, K-major)
__device__ __forceinline__ void gemm_pipe(
    const __nv_bfloat16* __restrict__ Ah, const __nv_bfloat16* __restrict__ Al,
    const __nv_bfloat16* __restrict__ Bh, const __nv_bfloat16* __restrict__ Bl,
    int K, int kstart, int nk, float acc[4][4][4])
{
    const int tid = threadIdx.x, lane = tid & 31, warp = tid >> 5;
    const int wm = warp >> 2, wn = warp & 3;
    const int lrow = lane & 15, lcolh = (lane >> 4) * 8;
    const uint32_t sbase = smem_u32(dyn_smem);

    const int r0 = tid >> 2, g0 = (tid & 3) * 8;
    const int r1 = (tid + 256) >> 2, g1 = ((tid + 256) & 3) * 8;
    const uint32_t ds0 = (uint32_t)(r0 * SPITCH + g0) * 2;
    const uint32_t ds1 = (uint32_t)(r1 * SPITCH + g1) * 2;

    {
        int kb = kstart;
        size_t o0 = (size_t)r0 * K + kb + g0;
        size_t o1 = (size_t)r1 * K + kb + g1;
        uint32_t b = sbase;
        cp16(b + AHOFF + ds0, Ah + o0); cp16(b + AHOFF + ds1, Ah + o1);
        cp16(b + ALOFF + ds0, Al + o0); cp16(b + ALOFF + ds1, Al + o1);
        cp16(b + BHOFF + ds0, Bh + o0); cp16(b + BHOFF + ds1, Bh + o1);
        cp16(b + BLOFF + ds0, Bl + o0); cp16(b + BLOFF + ds1, Bl + o1);
        asm volatile("cp.async.commit_group;");
    }

    for (int i = 0; i < nk; i++) {
        if (i + 1 < nk) {
            int kb = kstart + (i + 1) * 32;
            size_t o0 = (size_t)r0 * K + kb + g0;
            size_t o1 = (size_t)r1 * K + kb + g1;
            uint32_t b = sbase + ((i + 1) & 1) * STG_BYTES;
            cp16(b + AHOFF + ds0, Ah + o0); cp16(b + AHOFF + ds1, Ah + o1);
            cp16(b + ALOFF + ds0, Al + o0); cp16(b + ALOFF + ds1, Al + o1);
            cp16(b + BHOFF + ds0, Bh + o0); cp16(b + BHOFF + ds1, Bh + o1);
            cp16(b + BLOFF + ds0, Bl + o0); cp16(b + BLOFF + ds1, Bl + o1);
            asm volatile("cp.async.commit_group;");
            asm volatile("cp.async.wait_group 1;");
        } else {
            asm volatile("cp.async.wait_group 0;");
        }
        __syncthreads();
        mma_chunk((const __nv_bfloat16*)(dyn_smem + (i & 1) * STG_BYTES),
                  wm, wn, lrow, lcolh, acc);
        __syncthreads();
    }
}

// ---------------------------------------------------------------------------
// merged conversions: z 0-1 = activations, z 2-6 = weights
// ---------------------------------------------------------------------------
__global__ __launch_bounds__(256) void conv_all(
    const float* __restrict__ qx, const float* __restrict__ kvx,
    const float* __restrict__ Wq, const float* __restrict__ Wk,
    const float* __restrict__ Wv, const float* __restrict__ Wg,
    const float* __restrict__ Wo)
{
    int z = blockIdx.z;
    if (z < 2) {
        const float* src = z ? kvx : qx;
        __nv_bfloat16* hi = z ? g_akv_hi : g_aq_hi;
        __nv_bfloat16* lo = z ? g_akv_lo : g_aq_lo;
        int base = (blockIdx.y * 32 + blockIdx.x) * 256 + threadIdx.x;
        #pragma unroll
        for (int i = 0; i < 4; i++) {
            int idx = base + i * (1024 * 256);
            float x = src[idx];
            __nv_bfloat16 h = __float2bfloat16(x);
            hi[idx] = h;
            lo[idx] = __float2bfloat16(x - __bfloat162float(h));
        }
        return;
    }
    int w = z - 2;
    const float* in; int R, C; __nv_bfloat16 *oh, *ol;
    if (w < 4) {
        in = (w == 0) ? Wq : (w == 1) ? Wk : (w == 2) ? Wv : Wg;
        R = CDIM; C = HD; oh = g_wt_hi + (size_t)w * HD * CDIM; ol = g_wt_lo + (size_t)w * HD * CDIM;
    } else {
        in = Wo; R = HD; C = CDIM; oh = g_wot_hi; ol = g_wot_lo;
    }
    int c0 = blockIdx.x * 32, r0 = blockIdx.y * 32;
    if (c0 >= C || r0 >= R) return;
    __shared__ float t[32][33];
    int tx = threadIdx.x & 31, ty = threadIdx.x >> 5;
    for (int i = ty; i < 32; i += 8) t[i][tx] = in[(size_t)(r0 + i) * C + c0 + tx];
    __syncthreads();
    for (int i = ty; i < 32; i += 8) {
        float x = t[tx][i];
        __nv_bfloat16 h = __float2bfloat16(x);
        size_t o = (size_t)(c0 + i) * R + r0 + tx;
        oh[o] = h;
        ol[o] = __float2bfloat16(x - __bfloat162float(h));
    }
}

// ---------------------------------------------------------------------------
// projection GEMMs: grid (8, 32, 4). BK=32 pipelined. (natural grid — R12)
// ---------------------------------------------------------------------------
#define TPT 136

__global__ __launch_bounds__(256, 2) void mm_proj_tc()
{
    const int mat = blockIdx.z;
    const int m0 = blockIdx.y * 128, n0 = blockIdx.x * 128;
    const __nv_bfloat16* Ah = ((mat == 1 || mat == 2) ? g_akv_hi : g_aq_hi) + (size_t)m0 * CDIM;
    const __nv_bfloat16* Al = ((mat == 1 || mat == 2) ? g_akv_lo : g_aq_lo) + (size_t)m0 * CDIM;
    const __nv_bfloat16* Bh = g_wt_hi + (size_t)mat * HD * CDIM + (size_t)n0 * CDIM;
    const __nv_bfloat16* Bl = g_wt_lo + (size_t)mat * HD * CDIM + (size_t)n0 * CDIM;

    float acc[4][4][4] = {};
    gemm_pipe(Ah, Al, Bh, Bl, CDIM, 0, CDIM / 32, acc);

    const int tid = threadIdx.x, lane = tid & 31, warp = tid >> 5;
    const int wm = warp >> 2, wn = warp & 3;
    const int l4 = lane >> 2, lq = lane & 3;

    if (mat == 2) {
        __nv_bfloat16* sT = (__nv_bfloat16*)dyn_smem;
        #pragma unroll
        for (int pass = 0; pass < 2; pass++) {
            #pragma unroll
            for (int mt = 0; mt < 4; mt++) {
                #pragma unroll
                for (int nt = 0; nt < 4; nt++) {
                    #pragma unroll
                    for (int rr = 0; rr < 2; rr++) {
                        int ml = wm * 64 + mt * 16 + l4 + rr * 8;
                        int cl = wn * 32 + nt * 8 + lq * 2;
                        float v0 = acc[mt][nt][rr * 2], v1 = acc[mt][nt][rr * 2 + 1];
                        __nv_bfloat16 b0 = __float2bfloat16(v0), b1 = __float2bfloat16(v1);
                        if (pass == 0) {
                            sT[cl * TPT + ml] = b0;
                            sT[(cl + 1) * TPT + ml] = b1;
                        } else {
                            sT[cl * TPT + ml] = __float2bfloat16(v0 - __bfloat162float(b0));
                            sT[(cl + 1) * TPT + ml] = __float2bfloat16(v1 - __bfloat162float(b1));
                        }
                    }
                }
            }
            __syncthreads();
            {
                int cl = tid >> 1, half = tid & 1;
                int hh = (n0 + cl) >> 6, d = (n0 + cl) & 63;
                __nv_bfloat16* dst = (pass == 0 ? g_vth : g_vtl)
                                   + ((size_t)hh * DHEAD + d) * N_TOK + m0 + half * 64;
                const __nv_bfloat16* srcr = &sT[cl * TPT + half * 64];
                #pragma unroll
                for (int j = 0; j < 8; j++)
                    *(uint4*)&dst[j * 8] = *(const uint4*)&srcr[j * 8];
            }
            __syncthreads();
        }
        return;
    }

    #pragma unroll
    for (int mt = 0; mt < 4; mt++) {
        #pragma unroll
        for (int nt = 0; nt < 4; nt++) {
            #pragma unroll
            for (int rr = 0; rr < 2; rr++) {
                int m = m0 + wm * 64 + mt * 16 + l4 + rr * 8;
                int c = n0 + wn * 32 + nt * 8 + lq * 2;
                float v0 = acc[mt][nt][rr * 2], v1 = acc[mt][nt][rr * 2 + 1];
                int hh = c >> 6, d = c & 63;
                if (mat == 0) {
                    __nv_bfloat162 ph, pl;
                    split2(v0 * 0.125f, v1 * 0.125f, &ph, &pl);
                    size_t o = ((size_t)hh * N_TOK + m) * DHEAD + d;
                    *(__nv_bfloat162*)&g_qh[o] = ph;
                    *(__nv_bfloat162*)&g_ql[o] = pl;
                } else if (mat == 1) {
                    __nv_bfloat162 ph, pl;
                    split2(v0, v1, &ph, &pl);
                    size_t o = ((size_t)hh * N_TOK + m) * DHEAD + d;
                    *(__nv_bfloat162*)&g_kh[o] = ph;
                    *(__nv_bfloat162*)&g_kl[o] = pl;
                } else {
                    float2 v = make_float2(1.f / (1.f + expf(-v0)), 1.f / (1.f + expf(-v1)));
                    *(float2*)&g_gate[(size_t)m * HD + c] = v;
                }
            }
        }
    }
}

// ---------------------------------------------------------------------------
// output GEMM, split-K pipelined: grid (2, 32, KZ)
// ---------------------------------------------------------------------------
__global__ __launch_bounds__(256, 2) void mm_out_tc()
{
    const int m0 = blockIdx.y * 128, n0 = blockIdx.x * 128;
    const int kz = blockIdx.z;

    float acc[4][4][4] = {};
    gemm_pipe(g_og_hi + (size_t)m0 * HD, g_og_lo + (size_t)m0 * HD,
              g_wot_hi + (size_t)n0 * HD, g_wot_lo + (size_t)n0 * HD,
              HD, kz * (HD / KZ), (HD / KZ) / 32, acc);

    float* part = g_part + (size_t)kz * N_TOK * CDIM;
    const int lane = threadIdx.x & 31, warp = threadIdx.x >> 5;
    const int wm = warp >> 2, wn = warp & 3;
    const int l4 = lane >> 2, lq = lane & 3;
    #pragma unroll
    for (int mt = 0; mt < 4; mt++) {
        #pragma unroll
        for (int nt = 0; nt < 4; nt++) {
            #pragma unroll
            for (int rr = 0; rr < 2; rr++) {
                int m = m0 + wm * 64 + mt * 16 + l4 + rr * 8;
                int c = n0 + wn * 32 + nt * 8 + lq * 2;
                *(float2*)&part[(size_t)m * CDIM + c] =
                    make_float2(acc[mt][nt][rr * 2], acc[mt][nt][rr * 2 + 1]);
            }
        }
    }
}

__global__ __launch_bounds__(256) void reduce_out(float* __restrict__ out)
{
    int idx = (blockIdx.x * 256 + threadIdx.x) * 4;
    float4 a = *(const float4*)&g_part[idx];
    float4 b = *(const float4*)&g_part[N_TOK * CDIM + idx];
    float4 c = *(const float4*)&g_part[2 * N_TOK * CDIM + idx];
    float4 d = *(const float4*)&g_part[3 * N_TOK * CDIM + idx];
    float4 r = make_float4(a.x + b.x + c.x + d.x, a.y + b.y + c.y + d.y,
                           a.z + b.z + c.z + d.z, a.w + b.w + c.w + d.w);
    *(float4*)&out[idx] = r;
}

// ---------------------------------------------------------------------------
// tensor-core local attention — natural grid (HEADS, NTRUNK) (R12 version)
// ---------------------------------------------------------------------------
#define QP 72
#define VP 264

__global__ __launch_bounds__(256) void attn_tc(const float* __restrict__ bias)
{
    __nv_bfloat16* Sb = (__nv_bfloat16*)dyn_smem;
    __nv_bfloat16* sQh = Sb;
    __nv_bfloat16* sQl = Sb + 4608;
    __nv_bfloat16* sKh = Sb + 9216;
    __nv_bfloat16* sKl = Sb + 27648;
    __nv_bfloat16* sVh = Sb + 9216;
    __nv_bfloat16* sVl = Sb + 26112;
    float* sO = (float*)dyn_smem;
    float* pm = (float*)(dyn_smem + 92160);
    float* ps = (float*)(dyn_smem + 92672);

    const int h = blockIdx.x, t = blockIdx.y;
    const int tid = threadIdx.x, lane = tid & 31, warp = tid >> 5;
    const int wm = warp & 3, ch = warp >> 2;
    const int kbase = t * NQ - PADL;
    const int lrow = lane & 15, lcolh = (lane >> 4) * 8;
    const int l4 = lane >> 2, lq = lane & 3;

    {
        const __nv_bfloat16* qh = g_qh + ((size_t)h * N_TOK + t * NQ) * DHEAD;
        const __nv_bfloat16* ql = g_ql + ((size_t)h * N_TOK + t * NQ) * DHEAD;
        #pragma unroll
        for (int i = 0; i < 2; i++) {
            int idx = tid + i * 256;
            int r = idx >> 3, g = idx & 7;
            *(uint4*)&sQh[r * QP + g * 8] = *(const uint4*)&qh[idx * 8];
            *(uint4*)&sQl[r * QP + g * 8] = *(const uint4*)&ql[idx * 8];
        }
        #pragma unroll
        for (int i = 0; i < 8; i++) {
            int idx = tid + i * 256;
            int r = idx >> 3, g = idx & 7;
            int gk = kbase + r;
            uint4 vh = {0, 0, 0, 0}, vl = {0, 0, 0, 0};
            if (gk >= 0 && gk < N_TOK) {
                size_t src = ((size_t)h * N_TOK + gk) * DHEAD + g * 8;
                vh = *(const uint4*)&g_kh[src];
                vl = *(const uint4*)&g_kl[src];
            }
            *(uint4*)&sKh[r * QP + g * 8] = vh;
            *(uint4*)&sKl[r * QP + g * 8] = vl;
        }
    }

    // init accumulators with bias (loads overlap the smem fill + S mma)
    float acc[16][4];
    {
        const int r0 = t * NQ + wm * 16 + l4;
        const int c0 = kbase + ch * 128 + lq * 2;
        #pragma unroll
        for (int nt = 0; nt < 16; nt++) {
            int gc = c0 + nt * 8;
            if (gc >= 0 && gc < N_TOK) {
                float2 b0 = *(const float2*)&bias[(size_t)r0 * N_TOK + gc];
                float2 b1 = *(const float2*)&bias[(size_t)(r0 + 8) * N_TOK + gc];
                acc[nt][0] = b0.x; acc[nt][1] = b0.y;
                acc[nt][2] = b1.x; acc[nt][3] = b1.y;
            } else {
                acc[nt][0] = 0.f; acc[nt][1] = 0.f; acc[nt][2] = 0.f; acc[nt][3] = 0.f;
            }
        }
    }
    __syncthreads();

    uint32_t ah[4][4], al[4][4];
    #pragma unroll
    for (int kc = 0; kc < 4; kc++) {
        int ro = (wm * 16 + lrow) * QP + kc * 16 + lcolh;
        ldm_x4(smem_u32(&sQh[ro]), ah[kc]);
        ldm_x4(smem_u32(&sQl[ro]), al[kc]);
    }
    #pragma unroll
    for (int nt = 0; nt < 8; nt++) {
        #pragma unroll
        for (int kc = 0; kc < 4; kc++) {
            uint32_t bh[4], bl[4];
            int ro = (ch * 128 + nt * 16 + lrow) * QP + kc * 16 + lcolh;
            ldm_x4(smem_u32(&sKh[ro]), bh);
            ldm_x4(smem_u32(&sKl[ro]), bl);
            mma16816(acc[2 * nt],     ah[kc], bh[0], bh[2]);
            mma16816(acc[2 * nt],     al[kc], bh[0], bh[2]);
            mma16816(acc[2 * nt],     ah[kc], bl[0], bl[2]);
            mma16816(acc[2 * nt + 1], ah[kc], bh[1], bh[3]);
            mma16816(acc[2 * nt + 1], al[kc], bh[1], bh[3]);
            mma16816(acc[2 * nt + 1], ah[kc], bl[1], bl[3]);
        }
    }

    const int rloc = wm * 16 + l4;
    float mx0 = -1e30f, mx1 = -1e30f;
    #pragma unroll
    for (int nt = 0; nt < 16; nt++) {
        mx0 = fmaxf(mx0, fmaxf(acc[nt][0], acc[nt][1]));
        mx1 = fmaxf(mx1, fmaxf(acc[nt][2], acc[nt][3]));
    }
    mx0 = fmaxf(mx0, __shfl_xor_sync(0xffffffffu, mx0, 1));
    mx0 = fmaxf(mx0, __shfl_xor_sync(0xffffffffu, mx0, 2));
    mx1 = fmaxf(mx1, __shfl_xor_sync(0xffffffffu, mx1, 1));
    mx1 = fmaxf(mx1, __shfl_xor_sync(0xffffffffu, mx1, 2));
    if (lq == 0) { pm[ch * 64 + rloc] = mx0; pm[ch * 64 + rloc + 8] = mx1; }
    __syncthreads();   // all sK reads retired; pm visible

    // V load first (overlaps the exp/sum math below)
    #pragma unroll
    for (int i = 0; i < 8; i++) {
        int idx = tid + i * 256;
        int d = idx >> 5, g = idx & 31;
        int gk0 = kbase + g * 8;
        uint4 vh = {0, 0, 0, 0}, vl = {0, 0, 0, 0};
        if (gk0 >= 0 && gk0 < N_TOK) {
            size_t src = ((size_t)h * DHEAD + d) * N_TOK + gk0;
            vh = *(const uint4*)&g_vth[src];
            vl = *(const uint4*)&g_vtl[src];
        }
        *(uint4*)&sVh[d * VP + g * 8] = vh;
        *(uint4*)&sVl[d * VP + g * 8] = vl;
    }

    float M0 = fmaxf(pm[rloc], pm[64 + rloc]);
    float M1 = fmaxf(pm[rloc + 8], pm[64 + rloc + 8]);
    float s0 = 0.f, s1 = 0.f;
    #pragma unroll
    for (int nt = 0; nt < 16; nt++) {
        acc[nt][0] = __expf(acc[nt][0] - M0); s0 += acc[nt][0];
        acc[nt][1] = __expf(acc[nt][1] - M0); s0 += acc[nt][1];
        acc[nt][2] = __expf(acc[nt][2] - M1); s1 += acc[nt][2];
        acc[nt][3] = __expf(acc[nt][3] - M1); s1 += acc[nt][3];
    }
    s0 += __shfl_xor_sync(0xffffffffu, s0, 1);
    s0 += __shfl_xor_sync(0xffffffffu, s0, 2);
    s1 += __shfl_xor_sync(0xffffffffu, s1, 1);
    s1 += __shfl_xor_sync(0xffffffffu, s1, 2);
    if (lq == 0) { ps[ch * 64 + rloc] = s0; ps[ch * 64 + rloc + 8] = s1; }
    __syncthreads();   // ps visible + V resident

    float inv0 = 1.f / (ps[rloc] + ps[64 + rloc]);
    float inv1 = 1.f / (ps[rloc + 8] + ps[64 + rloc + 8]);
    #pragma unroll
    for (int nt = 0; nt < 16; nt++) {
        acc[nt][0] *= inv0; acc[nt][1] *= inv0;
        acc[nt][2] *= inv1; acc[nt][3] *= inv1;
    }

    float oacc[8][4];
    #pragma unroll
    for (int i = 0; i < 8; i++) { oacc[i][0] = 0.f; oacc[i][1] = 0.f; oacc[i][2] = 0.f; oacc[i][3] = 0.f; }
    #pragma unroll
    for (int kc = 0; kc < 8; kc++) {
        uint32_t awh[4], awl[4];
        #pragma unroll
        for (int f = 0; f < 4; f++) {
            int nt = 2 * kc + (f >> 1);
            int j = (f & 1) * 2;
            float x0 = acc[nt][j], x1 = acc[nt][j + 1];
            __nv_bfloat16 b0 = __float2bfloat16(x0), b1 = __float2bfloat16(x1);
            __nv_bfloat162 ph; ph.x = b0; ph.y = b1;
            awh[f] = *(uint32_t*)&ph;
            awl[f] = pack_bf16x2(x0 - __bfloat162float(b0), x1 - __bfloat162float(b1));
        }
        #pragma unroll
        for (int dg = 0; dg < 4; dg++) {
            uint32_t bh[4], bl[4];
            int ro = (dg * 16 + lrow) * VP + ch * 128 + kc * 16 + lcolh;
            ldm_x4(smem_u32(&sVh[ro]), bh);
            ldm_x4(smem_u32(&sVl[ro]), bl);
            mma16816(oacc[2 * dg],     awh, bh[0], bh[2]);
            mma16816(oacc[2 * dg],     awl, bh[0], bh[2]);
            mma16816(oacc[2 * dg],     awh, bl[0], bl[2]);
            mma16816(oacc[2 * dg + 1], awh, bh[1], bh[3]);
            mma16816(oacc[2 * dg + 1], awl, bh[1], bh[3]);
            mma16816(oacc[2 * dg + 1], awh, bl[1], bl[3]);
        }
    }

    __syncthreads();
    if (ch == 1) {
        #pragma unroll
        for (int nt = 0; nt < 8; nt++) {
            int c = nt * 8 + lq * 2;
            sO[(wm * 16 + l4) * 66 + c] = oacc[nt][0];
            sO[(wm * 16 + l4) * 66 + c + 1] = oacc[nt][1];
            sO[(wm * 16 + l4 + 8) * 66 + c] = oacc[nt][2];
            sO[(wm * 16 + l4 + 8) * 66 + c + 1] = oacc[nt][3];
        }
    }
    __syncthreads();
    if (ch == 0) {
        #pragma unroll
        for (int nt = 0; nt < 8; nt++) {
            int r = wm * 16 + l4, c = nt * 8 + lq * 2;
            #pragma unroll
            for (int half = 0; half < 2; half++) {
                int rr = r + half * 8;
                float v0 = oacc[nt][half * 2]     + sO[rr * 66 + c];
                float v1 = oacc[nt][half * 2 + 1] + sO[rr * 66 + c + 1];
                size_t gi = (size_t)(t * NQ + rr) * HD + h * DHEAD + c;
                float2 gt = *(const float2*)&g_gate[gi];
                __nv_bfloat162 ph, pl;
                split2(v0 * gt.x, v1 * gt.y, &ph, &pl);
                *(__nv_bfloat162*)&g_og_hi[gi] = ph;
                *(__nv_bfloat162*)&g_og_lo[gi] = pl;
            }
        }
    }
}

// ---------------------------------------------------------------------------
extern "C" void kernel_launch(void* const* d_in, const int* in_sizes, int n_in,
                              void* d_out, int out_size)
{
    const float* qx   = (const float*)d_in[0];
    const float* kvx  = (const float*)d_in[1];
    const float* bias = (const float*)d_in[2];
    const float* Wq   = (const float*)d_in[3];
    const float* Wk   = (const float*)d_in[4];
    const float* Wv   = (const float*)d_in[5];
    const float* Wg   = (const float*)d_in[6];
    const float* Wo   = (const float*)d_in[7];
    float* out = (float*)d_out;

    static int configured = 0;
    if (!configured) {
        cudaFuncSetAttribute(attn_tc, cudaFuncAttributeMaxDynamicSharedMemorySize, 93184);
        cudaFuncSetAttribute(mm_proj_tc, cudaFuncAttributeMaxDynamicSharedMemorySize, SMEM_GEMM);
        cudaFuncSetAttribute(mm_out_tc, cudaFuncAttributeMaxDynamicSharedMemorySize, SMEM_GEMM);
        configured = 1;
    }

    conv_all<<<dim3(32, 32, 7), 256>>>(qx, kvx, Wq, Wk, Wv, Wg, Wo);

    mm_proj_tc<<<dim3(HD / 128, N_TOK / 128, 4), 256, SMEM_GEMM>>>();

    attn_tc<<<dim3(HEADS, NTRUNK), 256, 93184>>>(bias);

    mm_out_tc<<<dim3(CDIM / 128, N_TOK / 128, KZ), 256, SMEM_GEMM>>>();
    reduce_out<<<N_TOK * CDIM / 1024, 256>>>(out);
}

// round 15
// speedup vs baseline: 1.1646x; 1.0089x over previous
#include <cuda_runtime.h>
#include <cuda_bf16.h>
#include <math.h>
#include <stdint.h>

#define N_TOK 4096
#define CDIM 256
#define HEADS 16
#define DHEAD 64
#define HD 1024
#define NQ 64
#define NKEY 256
#define NTRUNK 64
#define PADL 96
#define KZ 8

extern __shared__ char dyn_smem[];

// ---------------- scratch (device globals) ----------------
__device__ float g_gate[N_TOK * HD];
__device__ float g_part[KZ * N_TOK * CDIM];

__device__ __align__(16) __nv_bfloat16 g_aq_hi[N_TOK * CDIM];
__device__ __align__(16) __nv_bfloat16 g_aq_lo[N_TOK * CDIM];
__device__ __align__(16) __nv_bfloat16 g_akv_hi[N_TOK * CDIM];
__device__ __align__(16) __nv_bfloat16 g_akv_lo[N_TOK * CDIM];
__device__ __align__(16) __nv_bfloat16 g_wt_hi[4 * HD * CDIM];   // [mat][n][k]
__device__ __align__(16) __nv_bfloat16 g_wt_lo[4 * HD * CDIM];
__device__ __align__(16) __nv_bfloat16 g_wot_hi[CDIM * HD];      // [n][k]
__device__ __align__(16) __nv_bfloat16 g_wot_lo[CDIM * HD];
__device__ __align__(16) __nv_bfloat16 g_og_hi[N_TOK * HD];
__device__ __align__(16) __nv_bfloat16 g_og_lo[N_TOK * HD];

// attention operands (bf16 hi/lo), q pre-scaled by 1/8
__device__ __align__(16) __nv_bfloat16 g_qh[HEADS * N_TOK * DHEAD];
__device__ __align__(16) __nv_bfloat16 g_ql[HEADS * N_TOK * DHEAD];
__device__ __align__(16) __nv_bfloat16 g_kh[HEADS * N_TOK * DHEAD];
__device__ __align__(16) __nv_bfloat16 g_kl[HEADS * N_TOK * DHEAD];
__device__ __align__(16) __nv_bfloat16 g_vth[HEADS * DHEAD * N_TOK]; // [h][d][n]
__device__ __align__(16) __nv_bfloat16 g_vtl[HEADS * DHEAD * N_TOK];

// ---------------- helpers ----------------
__device__ __forceinline__ uint32_t smem_u32(const void* p) {
    uint32_t a;
    asm("{ .reg .u64 t; cvta.to.shared.u64 t, %1; cvt.u32.u64 %0, t; }" : "=r"(a) : "l"(p));
    return a;
}

__device__ __forceinline__ void ldm_x4(uint32_t addr, uint32_t* r) {
    asm volatile("ldmatrix.sync.aligned.m8n8.x4.shared.b16 {%0,%1,%2,%3}, [%4];"
                 : "=r"(r[0]), "=r"(r[1]), "=r"(r[2]), "=r"(r[3]) : "r"(addr));
}

__device__ __forceinline__ void mma16816(float* c, const uint32_t* a, uint32_t b0, uint32_t b1) {
    asm volatile(
        "mma.sync.aligned.m16n8k16.row.col.f32.bf16.bf16.f32 "
        "{%0,%1,%2,%3}, {%4,%5,%6,%7}, {%8,%9}, {%0,%1,%2,%3};"
        : "+f"(c[0]), "+f"(c[1]), "+f"(c[2]), "+f"(c[3])
        : "r"(a[0]), "r"(a[1]), "r"(a[2]), "r"(a[3]), "r"(b0), "r"(b1));
}

__device__ __forceinline__ uint32_t pack_bf16x2(float x0, float x1) {
    __nv_bfloat162 p;
    p.x = __float2bfloat16(x0);
    p.y = __float2bfloat16(x1);
    return *(uint32_t*)&p;
}

__device__ __forceinline__ void split2(float x0, float x1,
                                       __nv_bfloat162* hi, __nv_bfloat162* lo) {
    __nv_bfloat16 b0 = __float2bfloat16(x0), b1 = __float2bfloat16(x1);
    hi->x = b0; hi->y = b1;
    lo->x = __float2bfloat16(x0 - __bfloat162float(b0));
    lo->y = __float2bfloat16(x1 - __bfloat162float(b1));
}

__device__ __forceinline__ void cp16(uint32_t d, const void* s) {
    asm volatile("cp.async.cg.shared.global [%0], [%1], 16;" :: "r"(d), "l"(s));
}

// GEMM smem: BK=32, pitch 40 halfwords; 4 regions of 10240 B; 2 stages.
#define SPITCH 40
#define RGN (128 * SPITCH)
#define AHOFF 0
#define ALOFF 10240
#define BHOFF 20480
#define BLOFF 30720
#define STG_BYTES 40960
#define SMEM_GEMM (2 * STG_BYTES)

// NP = number of mma passes: 3 = full bf16x3, 2 = drop Ah*Bl (gate only)
template<int NP>
__device__ __forceinline__ void mma_chunk(
    const __nv_bfloat16* sbuf, int wm, int wn, int lrow, int lcolh, float acc[4][4][4])
{
    #pragma unroll
    for (int ks = 0; ks < 2; ks++) {
        uint32_t ah[4][4], al[4][4];
        #pragma unroll
        for (int mt = 0; mt < 4; mt++) {
            int ro = (wm * 64 + mt * 16 + lrow) * SPITCH + ks * 16 + lcolh;
            ldm_x4(smem_u32(&sbuf[ro]), ah[mt]);
            ldm_x4(smem_u32(&sbuf[RGN + ro]), al[mt]);
        }
        #pragma unroll
        for (int bt = 0; bt < 2; bt++) {
            uint32_t bh[4], bl[4];
            int ro = (wn * 32 + bt * 16 + lrow) * SPITCH + ks * 16 + lcolh;
            ldm_x4(smem_u32(&sbuf[2 * RGN + ro]), bh);
            if (NP == 3) ldm_x4(smem_u32(&sbuf[3 * RGN + ro]), bl);
            #pragma unroll
            for (int mt = 0; mt < 4; mt++) {
                mma16816(acc[mt][bt * 2],     ah[mt], bh[0], bh[2]);
                mma16816(acc[mt][bt * 2],     al[mt], bh[0], bh[2]);
                if (NP == 3) mma16816(acc[mt][bt * 2], ah[mt], bl[0], bl[2]);
                mma16816(acc[mt][bt * 2 + 1], ah[mt], bh[1], bh[3]);
                mma16816(acc[mt][bt * 2 + 1], al[mt], bh[1], bh[3]);
                if (NP == 3) mma16816(acc[mt][bt * 2 + 1], ah[mt], bl[1], bl[3]);
            }
        }
    }
}

// cp.async 2-stage pipelined GEMM mainloop (all operands bf16, K-major)
template<int NP>
__device__ __forceinline__ void gemm_pipe(
    const __nv_bfloat16* __restrict__ Ah, const __nv_bfloat16* __restrict__ Al,
    const __nv_bfloat16* __restrict__ Bh, const __nv_bfloat16* __restrict__ Bl,
    int K, int kstart, int nk, float acc[4][4][4])
{
    const int tid = threadIdx.x, lane = tid & 31, warp = tid >> 5;
    const int wm = warp >> 2, wn = warp & 3;
    const int lrow = lane & 15, lcolh = (lane >> 4) * 8;
    const uint32_t sbase = smem_u32(dyn_smem);

    const int r0 = tid >> 2, g0 = (tid & 3) * 8;
    const int r1 = (tid + 256) >> 2, g1 = ((tid + 256) & 3) * 8;
    const uint32_t ds0 = (uint32_t)(r0 * SPITCH + g0) * 2;
    const uint32_t ds1 = (uint32_t)(r1 * SPITCH + g1) * 2;

    {
        int kb = kstart;
        size_t o0 = (size_t)r0 * K + kb + g0;
        size_t o1 = (size_t)r1 * K + kb + g1;
        uint32_t b = sbase;
        cp16(b + AHOFF + ds0, Ah + o0); cp16(b + AHOFF + ds1, Ah + o1);
        cp16(b + ALOFF + ds0, Al + o0); cp16(b + ALOFF + ds1, Al + o1);
        cp16(b + BHOFF + ds0, Bh + o0); cp16(b + BHOFF + ds1, Bh + o1);
        if (NP == 3) { cp16(b + BLOFF + ds0, Bl + o0); cp16(b + BLOFF + ds1, Bl + o1); }
        asm volatile("cp.async.commit_group;");
    }

    for (int i = 0; i < nk; i++) {
        if (i + 1 < nk) {
            int kb = kstart + (i + 1) * 32;
            size_t o0 = (size_t)r0 * K + kb + g0;
            size_t o1 = (size_t)r1 * K + kb + g1;
            uint32_t b = sbase + ((i + 1) & 1) * STG_BYTES;
            cp16(b + AHOFF + ds0, Ah + o0); cp16(b + AHOFF + ds1, Ah + o1);
            cp16(b + ALOFF + ds0, Al + o0); cp16(b + ALOFF + ds1, Al + o1);
            cp16(b + BHOFF + ds0, Bh + o0); cp16(b + BHOFF + ds1, Bh + o1);
            if (NP == 3) { cp16(b + BLOFF + ds0, Bl + o0); cp16(b + BLOFF + ds1, Bl + o1); }
            asm volatile("cp.async.commit_group;");
            asm volatile("cp.async.wait_group 1;");
        } else {
            asm volatile("cp.async.wait_group 0;");
        }
        __syncthreads();
        mma_chunk<NP>((const __nv_bfloat16*)(dyn_smem + (i & 1) * STG_BYTES),
                      wm, wn, lrow, lcolh, acc);
        __syncthreads();
    }
}

// ---------------------------------------------------------------------------
// merged conversions: z 0-1 = activations, z 2-6 = weights
// ---------------------------------------------------------------------------
__global__ __launch_bounds__(256) void conv_all(
    const float* __restrict__ qx, const float* __restrict__ kvx,
    const float* __restrict__ Wq, const float* __restrict__ Wk,
    const float* __restrict__ Wv, const float* __restrict__ Wg,
    const float* __restrict__ Wo)
{
    int z = blockIdx.z;
    if (z < 2) {
        const float* src = z ? kvx : qx;
        __nv_bfloat16* hi = z ? g_akv_hi : g_aq_hi;
        __nv_bfloat16* lo = z ? g_akv_lo : g_aq_lo;
        int base = (blockIdx.y * 32 + blockIdx.x) * 256 + threadIdx.x;
        #pragma unroll
        for (int i = 0; i < 4; i++) {
            int idx = base + i * (1024 * 256);
            float x = src[idx];
            __nv_bfloat16 h = __float2bfloat16(x);
            hi[idx] = h;
            lo[idx] = __float2bfloat16(x - __bfloat162float(h));
        }
        return;
    }
    int w = z - 2;
    const float* in; int R, C; __nv_bfloat16 *oh, *ol;
    if (w < 4) {
        in = (w == 0) ? Wq : (w == 1) ? Wk : (w == 2) ? Wv : Wg;
        R = CDIM; C = HD; oh = g_wt_hi + (size_t)w * HD * CDIM; ol = g_wt_lo + (size_t)w * HD * CDIM;
    } else {
        in = Wo; R = HD; C = CDIM; oh = g_wot_hi; ol = g_wot_lo;
    }
    int c0 = blockIdx.x * 32, r0 = blockIdx.y * 32;
    if (c0 >= C || r0 >= R) return;
    __shared__ float t[32][33];
    int tx = threadIdx.x & 31, ty = threadIdx.x >> 5;
    for (int i = ty; i < 32; i += 8) t[i][tx] = in[(size_t)(r0 + i) * C + c0 + tx];
    __syncthreads();
    for (int i = ty; i < 32; i += 8) {
        float x = t[tx][i];
        __nv_bfloat16 h = __float2bfloat16(x);
        size_t o = (size_t)(c0 + i) * R + r0 + tx;
        oh[o] = h;
        ol[o] = __float2bfloat16(x - __bfloat162float(h));
    }
}

// ---------------------------------------------------------------------------
// projection GEMMs: grid (8, 32, 4). BK=32 pipelined; gate uses 2-pass.
// ---------------------------------------------------------------------------
#define TPT 136

__global__ __launch_bounds__(256, 2) void mm_proj_tc()
{
    const int mat = blockIdx.z;
    const int m0 = blockIdx.y * 128, n0 = blockIdx.x * 128;
    const __nv_bfloat16* Ah = ((mat == 1 || mat == 2) ? g_akv_hi : g_aq_hi) + (size_t)m0 * CDIM;
    const __nv_bfloat16* Al = ((mat == 1 || mat == 2) ? g_akv_lo : g_aq_lo) + (size_t)m0 * CDIM;
    const __nv_bfloat16* Bh = g_wt_hi + (size_t)mat * HD * CDIM + (size_t)n0 * CDIM;
    const __nv_bfloat16* Bl = g_wt_lo + (size_t)mat * HD * CDIM + (size_t)n0 * CDIM;

    float acc[4][4][4] = {};
    if (mat == 3) gemm_pipe<2>(Ah, Al, Bh, Bl, CDIM, 0, CDIM / 32, acc);
    else          gemm_pipe<3>(Ah, Al, Bh, Bl, CDIM, 0, CDIM / 32, acc);

    const int tid = threadIdx.x, lane = tid & 31, warp = tid >> 5;
    const int wm = warp >> 2, wn = warp & 3;
    const int l4 = lane >> 2, lq = lane & 3;

    if (mat == 2) {
        __nv_bfloat16* sT = (__nv_bfloat16*)dyn_smem;
        #pragma unroll
        for (int pass = 0; pass < 2; pass++) {
            #pragma unroll
            for (int mt = 0; mt < 4; mt++) {
                #pragma unroll
                for (int nt = 0; nt < 4; nt++) {
                    #pragma unroll
                    for (int rr = 0; rr < 2; rr++) {
                        int ml = wm * 64 + mt * 16 + l4 + rr * 8;
                        int cl = wn * 32 + nt * 8 + lq * 2;
                        float v0 = acc[mt][nt][rr * 2], v1 = acc[mt][nt][rr * 2 + 1];
                        __nv_bfloat16 b0 = __float2bfloat16(v0), b1 = __float2bfloat16(v1);
                        if (pass == 0) {
                            sT[cl * TPT + ml] = b0;
                            sT[(cl + 1) * TPT + ml] = b1;
                        } else {
                            sT[cl * TPT + ml] = __float2bfloat16(v0 - __bfloat162float(b0));
                            sT[(cl + 1) * TPT + ml] = __float2bfloat16(v1 - __bfloat162float(b1));
                        }
                    }
                }
            }
            __syncthreads();
            {
                int cl = tid >> 1, half = tid & 1;
                int hh = (n0 + cl) >> 6, d = (n0 + cl) & 63;
                __nv_bfloat16* dst = (pass == 0 ? g_vth : g_vtl)
                                   + ((size_t)hh * DHEAD + d) * N_TOK + m0 + half * 64;
                const __nv_bfloat16* srcr = &sT[cl * TPT + half * 64];
                #pragma unroll
                for (int j = 0; j < 8; j++)
                    *(uint4*)&dst[j * 8] = *(const uint4*)&srcr[j * 8];
            }
            __syncthreads();
        }
        return;
    }

    #pragma unroll
    for (int mt = 0; mt < 4; mt++) {
        #pragma unroll
        for (int nt = 0; nt < 4; nt++) {
            #pragma unroll
            for (int rr = 0; rr < 2; rr++) {
                int m = m0 + wm * 64 + mt * 16 + l4 + rr * 8;
                int c = n0 + wn * 32 + nt * 8 + lq * 2;
                float v0 = acc[mt][nt][rr * 2], v1 = acc[mt][nt][rr * 2 + 1];
                int hh = c >> 6, d = c & 63;
                if (mat == 0) {
                    __nv_bfloat162 ph, pl;
                    split2(v0 * 0.125f, v1 * 0.125f, &ph, &pl);
                    size_t o = ((size_t)hh * N_TOK + m) * DHEAD + d;
                    *(__nv_bfloat162*)&g_qh[o] = ph;
                    *(__nv_bfloat162*)&g_ql[o] = pl;
                } else if (mat == 1) {
                    __nv_bfloat162 ph, pl;
                    split2(v0, v1, &ph, &pl);
                    size_t o = ((size_t)hh * N_TOK + m) * DHEAD + d;
                    *(__nv_bfloat162*)&g_kh[o] = ph;
                    *(__nv_bfloat162*)&g_kl[o] = pl;
                } else {
                    float2 v = make_float2(1.f / (1.f + expf(-v0)), 1.f / (1.f + expf(-v1)));
                    *(float2*)&g_gate[(size_t)m * HD + c] = v;
                }
            }
        }
    }
}

// ---------------------------------------------------------------------------
// output GEMM, split-K pipelined: grid (2, 32, KZ=8)
// ---------------------------------------------------------------------------
__global__ __launch_bounds__(256, 2) void mm_out_tc()
{
    const int m0 = blockIdx.y * 128, n0 = blockIdx.x * 128;
    const int kz = blockIdx.z;

    float acc[4][4][4] = {};
    gemm_pipe<3>(g_og_hi + (size_t)m0 * HD, g_og_lo + (size_t)m0 * HD,
                 g_wot_hi + (size_t)n0 * HD, g_wot_lo + (size_t)n0 * HD,
                 HD, kz * (HD / KZ), (HD / KZ) / 32, acc);

    float* part = g_part + (size_t)kz * N_TOK * CDIM;
    const int lane = threadIdx.x & 31, warp = threadIdx.x >> 5;
    const int wm = warp >> 2, wn = warp & 3;
    const int l4 = lane >> 2, lq = lane & 3;
    #pragma unroll
    for (int mt = 0; mt < 4; mt++) {
        #pragma unroll
        for (int nt = 0; nt < 4; nt++) {
            #pragma unroll
            for (int rr = 0; rr < 2; rr++) {
                int m = m0 + wm * 64 + mt * 16 + l4 + rr * 8;
                int c = n0 + wn * 32 + nt * 8 + lq * 2;
                *(float2*)&part[(size_t)m * CDIM + c] =
                    make_float2(acc[mt][nt][rr * 2], acc[mt][nt][rr * 2 + 1]);
            }
        }
    }
}

__global__ __launch_bounds__(256) void reduce_out(float* __restrict__ out)
{
    int idx = (blockIdx.x * 256 + threadIdx.x) * 4;
    float4 r = *(const float4*)&g_part[idx];
    #pragma unroll
    for (int s = 1; s < KZ; s++) {
        float4 v = *(const float4*)&g_part[(size_t)s * N_TOK * CDIM + idx];
        r.x += v.x; r.y += v.y; r.z += v.z; r.w += v.w;
    }
    *(float4*)&out[idx] = r;
}

// ---------------------------------------------------------------------------
// tensor-core local attention — natural grid (HEADS, NTRUNK)
// ---------------------------------------------------------------------------
#define QP 72
#define VP 264

__global__ __launch_bounds__(256, 2) void attn_tc(const float* __restrict__ bias)
{
    __nv_bfloat16* Sb = (__nv_bfloat16*)dyn_smem;
    __nv_bfloat16* sQh = Sb;
    __nv_bfloat16* sQl = Sb + 4608;
    __nv_bfloat16* sKh = Sb + 9216;
    __nv_bfloat16* sKl = Sb + 27648;
    __nv_bfloat16* sVh = Sb + 9216;
    __nv_bfloat16* sVl = Sb + 26112;
    float* sO = (float*)dyn_smem;
    float* pm = (float*)(dyn_smem + 92160);
    float* ps = (float*)(dyn_smem + 92672);

    const int h = blockIdx.x, t = blockIdx.y;
    const int tid = threadIdx.x, lane = tid & 31, warp = tid >> 5;
    const int wm = warp & 3, ch = warp >> 2;
    const int kbase = t * NQ - PADL;
    const int lrow = lane & 15, lcolh = (lane >> 4) * 8;
    const int l4 = lane >> 2, lq = lane & 3;

    {
        const __nv_bfloat16* qh = g_qh + ((size_t)h * N_TOK + t * NQ) * DHEAD;
        const __nv_bfloat16* ql = g_ql + ((size_t)h * N_TOK + t * NQ) * DHEAD;
        #pragma unroll
        for (int i = 0; i < 2; i++) {
            int idx = tid + i * 256;
            int r = idx >> 3, g = idx & 7;
            *(uint4*)&sQh[r * QP + g * 8] = *(const uint4*)&qh[idx * 8];
            *(uint4*)&sQl[r * QP + g * 8] = *(const uint4*)&ql[idx * 8];
        }
        #pragma unroll
        for (int i = 0; i < 8; i++) {
            int idx = tid + i * 256;
            int r = idx >> 3, g = idx & 7;
            int gk = kbase + r;
            uint4 vh = {0, 0, 0, 0}, vl = {0, 0, 0, 0};
            if (gk >= 0 && gk < N_TOK) {
                size_t src = ((size_t)h * N_TOK + gk) * DHEAD + g * 8;
                vh = *(const uint4*)&g_kh[src];
                vl = *(const uint4*)&g_kl[src];
            }
            *(uint4*)&sKh[r * QP + g * 8] = vh;
            *(uint4*)&sKl[r * QP + g * 8] = vl;
        }
    }

    // init accumulators with bias (loads overlap the smem fill + S mma)
    float acc[16][4];
    {
        const int r0 = t * NQ + wm * 16 + l4;
        const int c0 = kbase + ch * 128 + lq * 2;
        #pragma unroll
        for (int nt = 0; nt < 16; nt++) {
            int gc = c0 + nt * 8;
            if (gc >= 0 && gc < N_TOK) {
                float2 b0 = *(const float2*)&bias[(size_t)r0 * N_TOK + gc];
                float2 b1 = *(const float2*)&bias[(size_t)(r0 + 8) * N_TOK + gc];
                acc[nt][0] = b0.x; acc[nt][1] = b0.y;
                acc[nt][2] = b1.x; acc[nt][3] = b1.y;
            } else {
                acc[nt][0] = 0.f; acc[nt][1] = 0.f; acc[nt][2] = 0.f; acc[nt][3] = 0.f;
            }
        }
    }
    __syncthreads();

    uint32_t ah[4][4], al[4][4];
    #pragma unroll
    for (int kc = 0; kc < 4; kc++) {
        int ro = (wm * 16 + lrow) * QP + kc * 16 + lcolh;
        ldm_x4(smem_u32(&sQh[ro]), ah[kc]);
        ldm_x4(smem_u32(&sQl[ro]), al[kc]);
    }
    #pragma unroll
    for (int nt = 0; nt < 8; nt++) {
        #pragma unroll
        for (int kc = 0; kc < 4; kc++) {
            uint32_t bh[4], bl[4];
            int ro = (ch * 128 + nt * 16 + lrow) * QP + kc * 16 + lcolh;
            ldm_x4(smem_u32(&sKh[ro]), bh);
            ldm_x4(smem_u32(&sKl[ro]), bl);
            mma16816(acc[2 * nt],     ah[kc], bh[0], bh[2]);
            mma16816(acc[2 * nt],     al[kc], bh[0], bh[2]);
            mma16816(acc[2 * nt],     ah[kc], bl[0], bl[2]);
            mma16816(acc[2 * nt + 1], ah[kc], bh[1], bh[3]);
            mma16816(acc[2 * nt + 1], al[kc], bh[1], bh[3]);
            mma16816(acc[2 * nt + 1], ah[kc], bl[1], bl[3]);
        }
    }

    const int rloc = wm * 16 + l4;
    float mx0 = -1e30f, mx1 = -1e30f;
    #pragma unroll
    for (int nt = 0; nt < 16; nt++) {
        mx0 = fmaxf(mx0, fmaxf(acc[nt][0], acc[nt][1]));
        mx1 = fmaxf(mx1, fmaxf(acc[nt][2], acc[nt][3]));
    }
    mx0 = fmaxf(mx0, __shfl_xor_sync(0xffffffffu, mx0, 1));
    mx0 = fmaxf(mx0, __shfl_xor_sync(0xffffffffu, mx0, 2));
    mx1 = fmaxf(mx1, __shfl_xor_sync(0xffffffffu, mx1, 1));
    mx1 = fmaxf(mx1, __shfl_xor_sync(0xffffffffu, mx1, 2));
    if (lq == 0) { pm[ch * 64 + rloc] = mx0; pm[ch * 64 + rloc + 8] = mx1; }
    __syncthreads();   // all sK reads retired; pm visible

    // V load first (overlaps the exp/sum math below)
    #pragma unroll
    for (int i = 0; i < 8; i++) {
        int idx = tid + i * 256;
        int d = idx >> 5, g = idx & 31;
        int gk0 = kbase + g * 8;
        uint4 vh = {0, 0, 0, 0}, vl = {0, 0, 0, 0};
        if (gk0 >= 0 && gk0 < N_TOK) {
            size_t src = ((size_t)h * DHEAD + d) * N_TOK + gk0;
            vh = *(const uint4*)&g_vth[src];
            vl = *(const uint4*)&g_vtl[src];
        }
        *(uint4*)&sVh[d * VP + g * 8] = vh;
        *(uint4*)&sVl[d * VP + g * 8] = vl;
    }

    float M0 = fmaxf(pm[rloc], pm[64 + rloc]);
    float M1 = fmaxf(pm[rloc + 8], pm[64 + rloc + 8]);
    float s0 = 0.f, s1 = 0.f;
    #pragma unroll
    for (int nt = 0; nt < 16; nt++) {
        acc[nt][0] = __expf(acc[nt][0] - M0); s0 += acc[nt][0];
        acc[nt][1] = __expf(acc[nt][1] - M0); s0 += acc[nt][1];
        acc[nt][2] = __expf(acc[nt][2] - M1); s1 += acc[nt][2];
        acc[nt][3] = __expf(acc[nt][3] - M1); s1 += acc[nt][3];
    }
    s0 += __shfl_xor_sync(0xffffffffu, s0, 1);
    s0 += __shfl_xor_sync(0xffffffffu, s0, 2);
    s1 += __shfl_xor_sync(0xffffffffu, s1, 1);
    s1 += __shfl_xor_sync(0xffffffffu, s1, 2);
    if (lq == 0) { ps[ch * 64 + rloc] = s0; ps[ch * 64 + rloc + 8] = s1; }
    __syncthreads();   // ps visible + V resident

    float inv0 = 1.f / (ps[rloc] + ps[64 + rloc]);
    float inv1 = 1.f / (ps[rloc + 8] + ps[64 + rloc + 8]);
    #pragma unroll
    for (int nt = 0; nt < 16; nt++) {
        acc[nt][0] *= inv0; acc[nt][1] *= inv0;
        acc[nt][2] *= inv1; acc[nt][3] *= inv1;
    }

    float oacc[8][4];
    #pragma unroll
    for (int i = 0; i < 8; i++) { oacc[i][0] = 0.f; oacc[i][1] = 0.f; oacc[i][2] = 0.f; oacc[i][3] = 0.f; }
    #pragma unroll
    for (int kc = 0; kc < 8; kc++) {
        uint32_t awh[4], awl[4];
        #pragma unroll
        for (int f = 0; f < 4; f++) {
            int nt = 2 * kc + (f >> 1);
            int j = (f & 1) * 2;
            float x0 = acc[nt][j], x1 = acc[nt][j + 1];
            __nv_bfloat16 b0 = __float2bfloat16(x0), b1 = __float2bfloat16(x1);
            __nv_bfloat162 ph; ph.x = b0; ph.y = b1;
            awh[f] = *(uint32_t*)&ph;
            awl[f] = pack_bf16x2(x0 - __bfloat162float(b0), x1 - __bfloat162float(b1));
        }
        #pragma unroll
        for (int dg = 0; dg < 4; dg++) {
            uint32_t bh[4], bl[4];
            int ro = (dg * 16 + lrow) * VP + ch * 128 + kc * 16 + lcolh;
            ldm_x4(smem_u32(&sVh[ro]), bh);
            ldm_x4(smem_u32(&sVl[ro]), bl);
            mma16816(oacc[2 * dg],     awh, bh[0], bh[2]);
            mma16816(oacc[2 * dg],     awl, bh[0], bh[2]);
            mma16816(oacc[2 * dg],     awh, bl[0], bl[2]);
            mma16816(oacc[2 * dg + 1], awh, bh[1], bh[3]);
            mma16816(oacc[2 * dg + 1], awl, bh[1], bh[3]);
            mma16816(oacc[2 * dg + 1], awh, bl[1], bl[3]);
        }
    }

    __syncthreads();
    if (ch == 1) {
        #pragma unroll
        for (int nt = 0; nt < 8; nt++) {
            int c = nt * 8 + lq * 2;
            sO[(wm * 16 + l4) * 66 + c] = oacc[nt][0];
            sO[(wm * 16 + l4) * 66 + c + 1] = oacc[nt][1];
            sO[(wm * 16 + l4 + 8) * 66 + c] = oacc[nt][2];
            sO[(wm * 16 + l4 + 8) * 66 + c + 1] = oacc[nt][3];
        }
    }
    __syncthreads();
    if (ch == 0) {
        #pragma unroll
        for (int nt = 0; nt < 8; nt++) {
            int r = wm * 16 + l4, c = nt * 8 + lq * 2;
            #pragma unroll
            for (int half = 0; half < 2; half++) {
                int rr = r + half * 8;
                float v0 = oacc[nt][half * 2]     + sO[rr * 66 + c];
                float v1 = oacc[nt][half * 2 + 1] + sO[rr * 66 + c + 1];
                size_t gi = (size_t)(t * NQ + rr) * HD + h * DHEAD + c;
                float2 gt = *(const float2*)&g_gate[gi];
                __nv_bfloat162 ph, pl;
                split2(v0 * gt.x, v1 * gt.y, &ph, &pl);
                *(__nv_bfloat162*)&g_og_hi[gi] = ph;
                *(__nv_bfloat162*)&g_og_lo[gi] = pl;
            }
        }
    }
}

// ---------------------------------------------------------------------------
extern "C" void kernel_launch(void* const* d_in, const int* in_sizes, int n_in,
                              void* d_out, int out_size)
{
    const float* qx   = (const float*)d_in[0];
    const float* kvx  = (const float*)d_in[1];
    const float* bias = (const float*)d_in[2];
    const float* Wq   = (const float*)d_in[3];
    const float* Wk   = (const float*)d_in[4];
    const float* Wv   = (const float*)d_in[5];
    const float* Wg   = (const float*)d_in[6];
    const float* Wo   = (const float*)d_in[7];
    float* out = (float*)d_out;

    static int configured = 0;
    if (!configured) {
        cudaFuncSetAttribute(attn_tc, cudaFuncAttributeMaxDynamicSharedMemorySize, 93184);
        cudaFuncSetAttribute(mm_proj_tc, cudaFuncAttributeMaxDynamicSharedMemorySize, SMEM_GEMM);
        cudaFuncSetAttribute(mm_out_tc, cudaFuncAttributeMaxDynamicSharedMemorySize, SMEM_GEMM);
        configured = 1;
    }

    conv_all<<<dim3(32, 32, 7), 256>>>(qx, kvx, Wq, Wk, Wv, Wg, Wo);

    mm_proj_tc<<<dim3(HD / 128, N_TOK / 128, 4), 256, SMEM_GEMM>>>();

    attn_tc<<<dim3(HEADS, NTRUNK), 256, 93184>>>(bias);

    mm_out_tc<<<dim3(CDIM / 128, N_TOK / 128, KZ), 256, SMEM_GEMM>>>();
    reduce_out<<<N_TOK * CDIM / 1024, 256>>>(out);
}